// round 14
// baseline (speedup 1.0000x reference)
#include <cuda_runtime.h>
#include <cstdint>

// RNN_16801912062326: leaky-ReLU Elman RNN scan.
// B=256, T=512, DIN=128, H=256, DOUT=64, fp32.
//
// Kernel 1 (scan): 64 clusters x 2 CTAs, 4 batches/cluster, h-recurrence ONLY
//   (x-projection evicted to kernel 2). GEMM1 per CTA: 384k x 128j x 4b with
//   packed fma.rn.f32x2; half of W register-resident, half in SMEM;
//   activations duplicated ((c,c) pairs) so LDS.128 yields f32x2 operands.
//   Hidden halves exchanged via st.shared::cluster + one barrier.cluster per
//   step (both primitives proven in the round-5 passing run).
// Kernel 2 (xgemm): x[b,t,:] = W_ho . h[b,t,:] + b_ho for t>=1; x[b,0,:]=x0.
//   Fully parallel, off the sequential critical path.

#define RNN_B    256
#define RNN_T    512
#define RNN_DIN  128
#define RNN_H    256
#define RNN_DOUT 64
#define BT       4
#define THREADS  256

// ---- scan SMEM layout (floats) ----
constexpr int WS_PITCH   = 132;
constexpr int WS_FLOATS  = 192 * WS_PITCH;        // 25344
constexpr int COMB_FLOATS= 2 * 384 * 8;           // 6144
constexpr int PART_FLOATS= 8 * 4 * 32 * 4;        // 4096

constexpr int OFF_W    = 0;
constexpr int OFF_COMB = OFF_W + WS_FLOATS;            // 25344
constexpr int OFF_PART = OFF_COMB + COMB_FLOATS;       // 31488
constexpr int OFF_BIH  = OFF_PART + PART_FLOATS;       // 35584
constexpr int SMEM_FLOATS = OFF_BIH + 128;             // 35712
constexpr int SMEM_BYTES  = SMEM_FLOATS * 4;           // 142848 B

static_assert(OFF_COMB % 4 == 0, "align");
static_assert(OFF_PART % 4 == 0, "align");

__device__ __forceinline__ void cluster_sync_inline() {
    asm volatile("barrier.cluster.arrive.aligned;\n\t"
                 "barrier.cluster.wait.aligned;" ::: "memory");
}
__device__ __forceinline__ void ffma2(uint64_t& acc, uint64_t a, uint64_t b) {
    asm("fma.rn.f32x2 %0, %1, %2, %0;" : "+l"(acc) : "l"(a), "l"(b));
}
__device__ __forceinline__ uint64_t pk2(float lo, float hi) {
    return (uint64_t)__float_as_uint(lo) | ((uint64_t)__float_as_uint(hi) << 32);
}
__device__ __forceinline__ float lo32(uint64_t v) { return __uint_as_float((uint32_t)v); }
__device__ __forceinline__ float hi32(uint64_t v) { return __uint_as_float((uint32_t)(v >> 32)); }

__global__ void __launch_bounds__(THREADS, 1) __cluster_dims__(2, 1, 1)
rnn_scan_kernel(const float* __restrict__ inputs,   // [B, T, DIN]
                const float* __restrict__ h0,       // [B, H]
                const float* __restrict__ W_ih,     // [256, 384]
                const float* __restrict__ b_ih,     // [H]
                float* __restrict__ hout)           // [B, T+1, H]
{
    extern __shared__ float smem[];
    const int tid  = threadIdx.x;
    const int rank = blockIdx.x & 1;
    const int cid  = blockIdx.x >> 1;
    const int b0   = cid * BT;

    float* Ws    = smem + OFF_W;          // [192][132]  smem-half of W_ih^T
    float* combA = smem + OFF_COMB;       // [2][384][8] dup (u rows 0..127, h 128..383)
    float* part  = smem + OFF_PART;       // [8][4][32] float4
    float* bihs  = smem + OFF_BIH;        // [128]

    // ---------------- setup ----------------
    // SMEM half of W_ih^T: rows (kc*24 + kk-24) for kk in [24,48), j 0..127.
    {
        const int jbase = rank * 128;
        for (int idx = tid; idx < 128 * 96; idx += THREADS) {
            int j  = idx / 96;
            int k4 = idx % 96;
            float4 v = *(const float4*)&W_ih[(size_t)(jbase + j) * 384 + 4 * k4];
            float vv[4] = {v.x, v.y, v.z, v.w};
            #pragma unroll
            for (int i = 0; i < 4; i++) {
                int k  = 4 * k4 + i;
                int kc_ = k / 48, kk = k % 48;
                if (kk >= 24)
                    Ws[(kc_ * 24 + (kk - 24)) * WS_PITCH + j] = vv[i];
            }
        }
    }
    if (tid < 128) bihs[tid] = b_ih[rank * 128 + tid];

    // register-resident W half: thread (kc = warp, jq = lane), kk in [0,24)
    const int kc = tid >> 5;
    const int jq = tid & 31;
    uint64_t w2reg[48];
    {
        const size_t jg0 = (size_t)(rank * 128 + 4 * jq);
        const int kb_ = kc * 48;
        #pragma unroll
        for (int kk = 0; kk < 24; kk++) {
            int k = kb_ + kk;
            w2reg[2*kk + 0] = pk2(W_ih[(jg0 + 0) * 384 + k], W_ih[(jg0 + 1) * 384 + k]);
            w2reg[2*kk + 1] = pk2(W_ih[(jg0 + 2) * 384 + k], W_ih[(jg0 + 3) * 384 + k]);
        }
    }

    // h0 -> comb buffer 0 (duplicated) + hout t=0
    {
        uint64_t* c64 = (uint64_t*)combA;
        for (int idx = tid; idx < RNN_H * BT; idx += THREADS) {
            int b  = idx >> 8;
            int jg = idx & 255;
            float v = h0[(size_t)(b0 + b) * RNN_H + jg];
            c64[(128 + jg) * 4 + b] = pk2(v, v);
            hout[(size_t)(b0 + b) * (RNN_T + 1) * RNN_H + jg] = v;
        }
    }
    // u_0 -> comb buffer 0 (duplicated)
    {
        int bb = tid >> 6;
        int kk = (tid & 63) * 2;
        float2 u = *(const float2*)&inputs[((size_t)(b0 + bb) * RNN_T + 0) * RNN_DIN + kk];
        uint64_t* c64 = (uint64_t*)combA;
        c64[kk * 4 + bb]       = pk2(u.x, u.x);
        c64[(kk + 1) * 4 + bb] = pk2(u.y, u.y);
    }
    __syncthreads();
    cluster_sync_inline();   // initial state visible cluster-wide

    // DSMEM peer base for combA
    uint32_t comb_peer_u32;
    {
        uint32_t comb_local_u32 = (uint32_t)__cvta_generic_to_shared(combA);
        uint32_t peer = rank ^ 1;
        asm("mapa.shared::cluster.u32 %0, %1, %2;"
            : "=r"(comb_peer_u32) : "r"(comb_local_u32), "r"(peer));
    }

    const int ubb = tid >> 6;
    const int ukk = (tid & 63) * 2;
    const int ej  = tid;               // epilogue j (tid<128)
    const int ei  = ej & 3, ejq = ej >> 2;
    const size_t hrow = (size_t)(RNN_T + 1) * RNN_H;
    const int kb = kc * 48;

    for (int t = 0; t < RNN_T; t++) {
        const int p = t & 1;
        const float* combp = combA + p * 3072;
        float*       combn = combA + (p ^ 1) * 3072;
        uint64_t*    combn64 = (uint64_t*)combn;

        // prefetch u_{t+1} (hidden under GEMM1)
        float2 unext = make_float2(0.f, 0.f);
        if (t + 1 < RNN_T)
            unext = *(const float2*)&inputs[((size_t)(b0 + ubb) * RNN_T + (t + 1)) * RNN_DIN + ukk];

        // ---- GEMM1: 4j x 4b x 48k per thread, packed f32x2 ----
        uint64_t acc[8];
        #pragma unroll
        for (int i = 0; i < 8; i++) acc[i] = 0;
        {
            const float* crow = combp + kb * 8;
            // register-W half: kk in [0,24)
            #pragma unroll
            for (int kk = 0; kk < 24; kk++) {
                ulonglong2 q01 = *(const ulonglong2*)(crow + kk * 8);
                ulonglong2 q23 = *(const ulonglong2*)(crow + kk * 8 + 4);
                uint64_t w0 = w2reg[2*kk], w1 = w2reg[2*kk + 1];
                ffma2(acc[0], w0, q01.x); ffma2(acc[1], w1, q01.x);
                ffma2(acc[2], w0, q01.y); ffma2(acc[3], w1, q01.y);
                ffma2(acc[4], w0, q23.x); ffma2(acc[5], w1, q23.x);
                ffma2(acc[6], w0, q23.y); ffma2(acc[7], w1, q23.y);
            }
            // smem-W half: kk in [24,48)
            const float* wrow = Ws + (kc * 24) * WS_PITCH + 4 * jq;
            #pragma unroll
            for (int kk = 0; kk < 24; kk++) {
                ulonglong2 wq = *(const ulonglong2*)(wrow + kk * WS_PITCH);
                ulonglong2 q01 = *(const ulonglong2*)(crow + (24 + kk) * 8);
                ulonglong2 q23 = *(const ulonglong2*)(crow + (24 + kk) * 8 + 4);
                ffma2(acc[0], wq.x, q01.x); ffma2(acc[1], wq.y, q01.x);
                ffma2(acc[2], wq.x, q01.y); ffma2(acc[3], wq.y, q01.y);
                ffma2(acc[4], wq.x, q23.x); ffma2(acc[5], wq.y, q23.x);
                ffma2(acc[6], wq.x, q23.y); ffma2(acc[7], wq.y, q23.y);
            }
        }
        // partial stores: part[kc][i][jq] float4 over b
        {
            float4 s0 = make_float4(lo32(acc[0]), lo32(acc[2]), lo32(acc[4]), lo32(acc[6]));
            float4 s1 = make_float4(hi32(acc[0]), hi32(acc[2]), hi32(acc[4]), hi32(acc[6]));
            float4 s2 = make_float4(lo32(acc[1]), lo32(acc[3]), lo32(acc[5]), lo32(acc[7]));
            float4 s3 = make_float4(hi32(acc[1]), hi32(acc[3]), hi32(acc[5]), hi32(acc[7]));
            float4* pb = (float4*)part + kc * 128 + jq;
            pb[0]  = s0;
            pb[32] = s1;
            pb[64] = s2;
            pb[96] = s3;
        }
        __syncthreads();

        // ---- epilogue: reduce 8 chunks, bias, leaky, publish h ----
        if (tid < 128) {
            float bias = bihs[ej];
            float4 s = make_float4(bias, bias, bias, bias);
            const float4* pb = (const float4*)part + ei * 32 + ejq;
            #pragma unroll
            for (int c = 0; c < 8; c++) {
                float4 v = pb[c * 128];
                s.x += v.x; s.y += v.y; s.z += v.z; s.w += v.w;
            }
            s.x = s.x >= 0.f ? s.x : 0.01f * s.x;
            s.y = s.y >= 0.f ? s.y : 0.01f * s.y;
            s.z = s.z >= 0.f ? s.z : 0.01f * s.z;
            s.w = s.w >= 0.f ? s.w : 0.01f * s.w;

            const int jg = rank * 128 + ej;
            uint64_t d0 = pk2(s.x, s.x), d1 = pk2(s.y, s.y);
            uint64_t d2 = pk2(s.z, s.z), d3 = pk2(s.w, s.w);
            // local next-buffer (duplicated)
            uint64_t* dst = combn64 + (128 + jg) * 4;
            dst[0] = d0; dst[1] = d1; dst[2] = d2; dst[3] = d3;
            // peer next-buffer (DSMEM, duplicated)
            uint32_t pa = comb_peer_u32 +
                          (uint32_t)((p ^ 1) * 12288 + (128 + jg) * 32);
            asm volatile("st.shared::cluster.b64 [%0], %1;" :: "r"(pa),      "l"(d0) : "memory");
            asm volatile("st.shared::cluster.b64 [%0], %1;" :: "r"(pa + 8),  "l"(d1) : "memory");
            asm volatile("st.shared::cluster.b64 [%0], %1;" :: "r"(pa + 16), "l"(d2) : "memory");
            asm volatile("st.shared::cluster.b64 [%0], %1;" :: "r"(pa + 24), "l"(d3) : "memory");
            // global h output, row t+1
            hout[(size_t)(b0 + 0) * hrow + (size_t)(t + 1) * RNN_H + jg] = s.x;
            hout[(size_t)(b0 + 1) * hrow + (size_t)(t + 1) * RNN_H + jg] = s.y;
            hout[(size_t)(b0 + 2) * hrow + (size_t)(t + 1) * RNN_H + jg] = s.z;
            hout[(size_t)(b0 + 3) * hrow + (size_t)(t + 1) * RNN_H + jg] = s.w;
        }

        // u_{t+1} into next buffer (local-only region, disjoint from h rows)
        if (t + 1 < RNN_T) {
            combn64[ukk * 4 + ubb]       = pk2(unext.x, unext.x);
            combn64[(ukk + 1) * 4 + ubb] = pk2(unext.y, unext.y);
        }

        // one cluster barrier per step: orders local epilogue/u writes AND
        // peer h-half stores before the next step's GEMM1 reads (release/
        // acquire at cluster scope; full barrier across both CTAs).
        cluster_sync_inline();
    }
}

// ---------------- kernel 2: x = h @ W_ho^T + b_ho ----------------
// grid (B, 5); block 128. Thread = one t-row; 32 packed-f32x2 accumulators
// over DOUT=64. W broadcast from SMEM (warp-uniform LDS.128), h reads
// conflict-free (pitch 257 -> bank = lane + k mod 32).

constexpr int XT_ROWS  = 128;
constexpr int XT_TILES = 5;                    // 5*128 >= 513
constexpr int XS_HS    = 0;                    // float hs[128][257]
constexpr int XS_WD    = XT_ROWS * 257 * 4;    // 131584, 16B aligned
constexpr int XS_BHO   = XS_WD + 256 * 32 * 8; // 197120
constexpr int XS_BYTES = XS_BHO + 64 * 4;      // 197376

__global__ void __launch_bounds__(128, 1)
xgemm_kernel(const float* __restrict__ hout,    // [B, T+1, H]
             const float* __restrict__ x0,      // [B, DOUT]
             const float* __restrict__ W_ho,    // [64, 256]
             const float* __restrict__ b_ho,    // [64]
             float* __restrict__ xout)          // [B, T+1, DOUT]
{
    extern __shared__ char xsm[];
    float*    hs  = (float*)(xsm + XS_HS);     // [128][257]
    uint64_t* wd  = (uint64_t*)(xsm + XS_WD);  // [256 k][32 jp]
    float*    bho = (float*)(xsm + XS_BHO);    // [64]

    const int tid = threadIdx.x;
    const int b   = blockIdx.x;
    const int t0  = blockIdx.y * XT_ROWS;
    const int nrows = min(XT_ROWS, (RNN_T + 1) - t0);

    // W transpose fill: wd[k][jp] = (W_ho[2jp][k], W_ho[2jp+1][k])
    for (int idx = tid; idx < 256 * 32; idx += 128) {
        int k = idx >> 5, jp = idx & 31;
        wd[k * 32 + jp] = pk2(W_ho[(size_t)(2 * jp) * 256 + k],
                              W_ho[(size_t)(2 * jp + 1) * 256 + k]);
    }
    if (tid < 64) bho[tid] = b_ho[tid];

    // h tile fill (coalesced rows -> pitch-257 smem)
    for (int idx = tid; idx < nrows * 64; idx += 128) {
        int r = idx >> 6, c4 = idx & 63;
        int tt = t0 + r;
        if (tt >= 1) {
            float4 v = *(const float4*)&hout[((size_t)b * (RNN_T + 1) + tt) * RNN_H + 4 * c4];
            float* d = hs + r * 257 + 4 * c4;
            d[0] = v.x; d[1] = v.y; d[2] = v.z; d[3] = v.w;
        }
    }
    __syncthreads();

    const int r = tid;
    if (r < nrows) {
        const int tt = t0 + r;
        float* orow = xout + ((size_t)b * (RNN_T + 1) + tt) * RNN_DOUT;
        if (tt == 0) {
            const float* src = x0 + (size_t)b * RNN_DOUT;
            #pragma unroll
            for (int c = 0; c < 16; c++)
                *(float4*)&orow[4 * c] = *(const float4*)&src[4 * c];
        } else {
            uint64_t acc[32];
            #pragma unroll
            for (int jp = 0; jp < 32; jp++)
                acc[jp] = pk2(bho[2 * jp], bho[2 * jp + 1]);
            const float* hrow = hs + r * 257;
            #pragma unroll 2
            for (int k = 0; k < 256; k++) {
                float hv = hrow[k];
                uint64_t h2 = pk2(hv, hv);
                const ulonglong2* wrow = (const ulonglong2*)(wd + k * 32);
                #pragma unroll
                for (int jj = 0; jj < 16; jj++) {
                    ulonglong2 w = wrow[jj];
                    ffma2(acc[2 * jj],     w.x, h2);
                    ffma2(acc[2 * jj + 1], w.y, h2);
                }
            }
            #pragma unroll
            for (int jp = 0; jp < 32; jp++)
                *(uint64_t*)&orow[2 * jp] = acc[jp];
        }
    }
}

extern "C" void kernel_launch(void* const* d_in, const int* in_sizes, int n_in,
                              void* d_out, int out_size) {
    (void)in_sizes; (void)n_in; (void)out_size;
    const float* inputs = (const float*)d_in[0];
    const float* x0     = (const float*)d_in[1];
    const float* h0     = (const float*)d_in[2];
    const float* W_ih   = (const float*)d_in[3];
    const float* b_ih   = (const float*)d_in[4];
    const float* W_ho   = (const float*)d_in[5];
    const float* b_ho   = (const float*)d_in[6];

    float* xout = (float*)d_out;                                   // [B, T+1, DOUT]
    float* hout = xout + (size_t)RNN_B * (RNN_T + 1) * RNN_DOUT;   // [B, T+1, H]

    cudaFuncSetAttribute(rnn_scan_kernel,
                         cudaFuncAttributeMaxDynamicSharedMemorySize, SMEM_BYTES);
    cudaFuncSetAttribute(xgemm_kernel,
                         cudaFuncAttributeMaxDynamicSharedMemorySize, XS_BYTES);

    rnn_scan_kernel<<<128, THREADS, SMEM_BYTES>>>(
        inputs, h0, W_ih, b_ih, hout);

    xgemm_kernel<<<dim3(RNN_B, XT_TILES), 128, XS_BYTES>>>(
        hout, x0, W_ho, b_ho, xout);
}

// round 15
// speedup vs baseline: 1.0713x; 1.0713x over previous
#include <cuda_runtime.h>
#include <cstdint>

// RNN_16801912062326: leaky-ReLU Elman RNN scan.
// B=256, T=512, DIN=128, H=256, DOUT=64, fp32.
//
// Kernel 1 (scan): UNCHANGED from the round-14 passing run (measured ~1465us).
//   64 clusters x 2 CTAs, h-recurrence only; GEMM1 384k x 128j x 4b with
//   packed fma.rn.f32x2; st.shared::cluster + 1 barrier.cluster per step.
// Kernel 2 (xgemm): REWRITTEN for occupancy. Round-14 profile: 329.6us at
//   occ=5.8% (197KB smem -> 1 CTA/SM -> 1 warp/SMSP, 9 waves). Fix: drop the
//   h staging tile (h is read once; stream it from gmem), smem = W only
//   (64.3KB) -> 2 CTAs/SM, 16 warps/SM, grid 513 blocks ~ 1.7 waves.
//   Inner algebra identical to the silicon-proven round-14 version.

#define RNN_B    256
#define RNN_T    512
#define RNN_DIN  128
#define RNN_H    256
#define RNN_DOUT 64
#define BT       4
#define THREADS  256

// ---- scan SMEM layout (floats) ----
constexpr int WS_PITCH   = 132;
constexpr int WS_FLOATS  = 192 * WS_PITCH;        // 25344
constexpr int COMB_FLOATS= 2 * 384 * 8;           // 6144
constexpr int PART_FLOATS= 8 * 4 * 32 * 4;        // 4096

constexpr int OFF_W    = 0;
constexpr int OFF_COMB = OFF_W + WS_FLOATS;            // 25344
constexpr int OFF_PART = OFF_COMB + COMB_FLOATS;       // 31488
constexpr int OFF_BIH  = OFF_PART + PART_FLOATS;       // 35584
constexpr int SMEM_FLOATS = OFF_BIH + 128;             // 35712
constexpr int SMEM_BYTES  = SMEM_FLOATS * 4;           // 142848 B

static_assert(OFF_COMB % 4 == 0, "align");
static_assert(OFF_PART % 4 == 0, "align");

__device__ __forceinline__ void cluster_sync_inline() {
    asm volatile("barrier.cluster.arrive.aligned;\n\t"
                 "barrier.cluster.wait.aligned;" ::: "memory");
}
__device__ __forceinline__ void ffma2(uint64_t& acc, uint64_t a, uint64_t b) {
    asm("fma.rn.f32x2 %0, %1, %2, %0;" : "+l"(acc) : "l"(a), "l"(b));
}
__device__ __forceinline__ uint64_t pk2(float lo, float hi) {
    return (uint64_t)__float_as_uint(lo) | ((uint64_t)__float_as_uint(hi) << 32);
}
__device__ __forceinline__ float lo32(uint64_t v) { return __uint_as_float((uint32_t)v); }
__device__ __forceinline__ float hi32(uint64_t v) { return __uint_as_float((uint32_t)(v >> 32)); }

__global__ void __launch_bounds__(THREADS, 1) __cluster_dims__(2, 1, 1)
rnn_scan_kernel(const float* __restrict__ inputs,   // [B, T, DIN]
                const float* __restrict__ h0,       // [B, H]
                const float* __restrict__ W_ih,     // [256, 384]
                const float* __restrict__ b_ih,     // [H]
                float* __restrict__ hout)           // [B, T+1, H]
{
    extern __shared__ float smem[];
    const int tid  = threadIdx.x;
    const int rank = blockIdx.x & 1;
    const int cid  = blockIdx.x >> 1;
    const int b0   = cid * BT;

    float* Ws    = smem + OFF_W;          // [192][132]  smem-half of W_ih^T
    float* combA = smem + OFF_COMB;       // [2][384][8] dup (u rows 0..127, h 128..383)
    float* part  = smem + OFF_PART;       // [8][4][32] float4
    float* bihs  = smem + OFF_BIH;        // [128]

    // ---------------- setup ----------------
    {
        const int jbase = rank * 128;
        for (int idx = tid; idx < 128 * 96; idx += THREADS) {
            int j  = idx / 96;
            int k4 = idx % 96;
            float4 v = *(const float4*)&W_ih[(size_t)(jbase + j) * 384 + 4 * k4];
            float vv[4] = {v.x, v.y, v.z, v.w};
            #pragma unroll
            for (int i = 0; i < 4; i++) {
                int k  = 4 * k4 + i;
                int kc_ = k / 48, kk = k % 48;
                if (kk >= 24)
                    Ws[(kc_ * 24 + (kk - 24)) * WS_PITCH + j] = vv[i];
            }
        }
    }
    if (tid < 128) bihs[tid] = b_ih[rank * 128 + tid];

    // register-resident W half: thread (kc = warp, jq = lane), kk in [0,24)
    const int kc = tid >> 5;
    const int jq = tid & 31;
    uint64_t w2reg[48];
    {
        const size_t jg0 = (size_t)(rank * 128 + 4 * jq);
        const int kb_ = kc * 48;
        #pragma unroll
        for (int kk = 0; kk < 24; kk++) {
            int k = kb_ + kk;
            w2reg[2*kk + 0] = pk2(W_ih[(jg0 + 0) * 384 + k], W_ih[(jg0 + 1) * 384 + k]);
            w2reg[2*kk + 1] = pk2(W_ih[(jg0 + 2) * 384 + k], W_ih[(jg0 + 3) * 384 + k]);
        }
    }

    // h0 -> comb buffer 0 (duplicated) + hout t=0
    {
        uint64_t* c64 = (uint64_t*)combA;
        for (int idx = tid; idx < RNN_H * BT; idx += THREADS) {
            int b  = idx >> 8;
            int jg = idx & 255;
            float v = h0[(size_t)(b0 + b) * RNN_H + jg];
            c64[(128 + jg) * 4 + b] = pk2(v, v);
            hout[(size_t)(b0 + b) * (RNN_T + 1) * RNN_H + jg] = v;
        }
    }
    // u_0 -> comb buffer 0 (duplicated)
    {
        int bb = tid >> 6;
        int kk = (tid & 63) * 2;
        float2 u = *(const float2*)&inputs[((size_t)(b0 + bb) * RNN_T + 0) * RNN_DIN + kk];
        uint64_t* c64 = (uint64_t*)combA;
        c64[kk * 4 + bb]       = pk2(u.x, u.x);
        c64[(kk + 1) * 4 + bb] = pk2(u.y, u.y);
    }
    __syncthreads();
    cluster_sync_inline();   // initial state visible cluster-wide

    // DSMEM peer base for combA
    uint32_t comb_peer_u32;
    {
        uint32_t comb_local_u32 = (uint32_t)__cvta_generic_to_shared(combA);
        uint32_t peer = rank ^ 1;
        asm("mapa.shared::cluster.u32 %0, %1, %2;"
            : "=r"(comb_peer_u32) : "r"(comb_local_u32), "r"(peer));
    }

    const int ubb = tid >> 6;
    const int ukk = (tid & 63) * 2;
    const int ej  = tid;               // epilogue j (tid<128)
    const int ei  = ej & 3, ejq = ej >> 2;
    const size_t hrow = (size_t)(RNN_T + 1) * RNN_H;
    const int kb = kc * 48;

    for (int t = 0; t < RNN_T; t++) {
        const int p = t & 1;
        const float* combp = combA + p * 3072;
        float*       combn = combA + (p ^ 1) * 3072;
        uint64_t*    combn64 = (uint64_t*)combn;

        // prefetch u_{t+1} (hidden under GEMM1)
        float2 unext = make_float2(0.f, 0.f);
        if (t + 1 < RNN_T)
            unext = *(const float2*)&inputs[((size_t)(b0 + ubb) * RNN_T + (t + 1)) * RNN_DIN + ukk];

        // ---- GEMM1: 4j x 4b x 48k per thread, packed f32x2 ----
        uint64_t acc[8];
        #pragma unroll
        for (int i = 0; i < 8; i++) acc[i] = 0;
        {
            const float* crow = combp + kb * 8;
            // register-W half: kk in [0,24)
            #pragma unroll
            for (int kk = 0; kk < 24; kk++) {
                ulonglong2 q01 = *(const ulonglong2*)(crow + kk * 8);
                ulonglong2 q23 = *(const ulonglong2*)(crow + kk * 8 + 4);
                uint64_t w0 = w2reg[2*kk], w1 = w2reg[2*kk + 1];
                ffma2(acc[0], w0, q01.x); ffma2(acc[1], w1, q01.x);
                ffma2(acc[2], w0, q01.y); ffma2(acc[3], w1, q01.y);
                ffma2(acc[4], w0, q23.x); ffma2(acc[5], w1, q23.x);
                ffma2(acc[6], w0, q23.y); ffma2(acc[7], w1, q23.y);
            }
            // smem-W half: kk in [24,48)
            const float* wrow = Ws + (kc * 24) * WS_PITCH + 4 * jq;
            #pragma unroll
            for (int kk = 0; kk < 24; kk++) {
                ulonglong2 wq = *(const ulonglong2*)(wrow + kk * WS_PITCH);
                ulonglong2 q01 = *(const ulonglong2*)(crow + (24 + kk) * 8);
                ulonglong2 q23 = *(const ulonglong2*)(crow + (24 + kk) * 8 + 4);
                ffma2(acc[0], wq.x, q01.x); ffma2(acc[1], wq.y, q01.x);
                ffma2(acc[2], wq.x, q01.y); ffma2(acc[3], wq.y, q01.y);
                ffma2(acc[4], wq.x, q23.x); ffma2(acc[5], wq.y, q23.x);
                ffma2(acc[6], wq.x, q23.y); ffma2(acc[7], wq.y, q23.y);
            }
        }
        // partial stores: part[kc][i][jq] float4 over b
        {
            float4 s0 = make_float4(lo32(acc[0]), lo32(acc[2]), lo32(acc[4]), lo32(acc[6]));
            float4 s1 = make_float4(hi32(acc[0]), hi32(acc[2]), hi32(acc[4]), hi32(acc[6]));
            float4 s2 = make_float4(lo32(acc[1]), lo32(acc[3]), lo32(acc[5]), lo32(acc[7]));
            float4 s3 = make_float4(hi32(acc[1]), hi32(acc[3]), hi32(acc[5]), hi32(acc[7]));
            float4* pb = (float4*)part + kc * 128 + jq;
            pb[0]  = s0;
            pb[32] = s1;
            pb[64] = s2;
            pb[96] = s3;
        }
        __syncthreads();

        // ---- epilogue: reduce 8 chunks, bias, leaky, publish h ----
        if (tid < 128) {
            float bias = bihs[ej];
            float4 s = make_float4(bias, bias, bias, bias);
            const float4* pb = (const float4*)part + ei * 32 + ejq;
            #pragma unroll
            for (int c = 0; c < 8; c++) {
                float4 v = pb[c * 128];
                s.x += v.x; s.y += v.y; s.z += v.z; s.w += v.w;
            }
            s.x = s.x >= 0.f ? s.x : 0.01f * s.x;
            s.y = s.y >= 0.f ? s.y : 0.01f * s.y;
            s.z = s.z >= 0.f ? s.z : 0.01f * s.z;
            s.w = s.w >= 0.f ? s.w : 0.01f * s.w;

            const int jg = rank * 128 + ej;
            uint64_t d0 = pk2(s.x, s.x), d1 = pk2(s.y, s.y);
            uint64_t d2 = pk2(s.z, s.z), d3 = pk2(s.w, s.w);
            // local next-buffer (duplicated)
            uint64_t* dst = combn64 + (128 + jg) * 4;
            dst[0] = d0; dst[1] = d1; dst[2] = d2; dst[3] = d3;
            // peer next-buffer (DSMEM, duplicated)
            uint32_t pa = comb_peer_u32 +
                          (uint32_t)((p ^ 1) * 12288 + (128 + jg) * 32);
            asm volatile("st.shared::cluster.b64 [%0], %1;" :: "r"(pa),      "l"(d0) : "memory");
            asm volatile("st.shared::cluster.b64 [%0], %1;" :: "r"(pa + 8),  "l"(d1) : "memory");
            asm volatile("st.shared::cluster.b64 [%0], %1;" :: "r"(pa + 16), "l"(d2) : "memory");
            asm volatile("st.shared::cluster.b64 [%0], %1;" :: "r"(pa + 24), "l"(d3) : "memory");
            // global h output, row t+1
            hout[(size_t)(b0 + 0) * hrow + (size_t)(t + 1) * RNN_H + jg] = s.x;
            hout[(size_t)(b0 + 1) * hrow + (size_t)(t + 1) * RNN_H + jg] = s.y;
            hout[(size_t)(b0 + 2) * hrow + (size_t)(t + 1) * RNN_H + jg] = s.z;
            hout[(size_t)(b0 + 3) * hrow + (size_t)(t + 1) * RNN_H + jg] = s.w;
        }

        // u_{t+1} into next buffer (local-only region, disjoint from h rows)
        if (t + 1 < RNN_T) {
            combn64[ukk * 4 + ubb]       = pk2(unext.x, unext.x);
            combn64[(ukk + 1) * 4 + ubb] = pk2(unext.y, unext.y);
        }

        // one cluster barrier per step: orders local epilogue/u writes AND
        // peer h-half stores before the next step's GEMM1 reads.
        cluster_sync_inline();
    }
}

// ---------------- kernel 2: x = h @ W_ho^T + b_ho (occupancy-fixed) ----------------
// grid 513 blocks x 256 threads; thread = one global row g = b*513 + t.
// hout is [B][513][256] so hrow = hout + g*256; xout row = xout + g*64.
// SMEM = W only (wd 64KB + bho) -> 2 CTAs/SM, 16 warps/SM (vs 4 in round 14).
// h streamed from gmem as float4 (read once; every fetched byte used).
// Inner algebra identical to the round-14 silicon-proven version.

constexpr int XROWS_TOTAL = RNN_B * (RNN_T + 1);       // 131328 = 513*256
constexpr int XBLOCKS     = 513;
constexpr int XS2_WD      = 0;                         // u64 wd[256][32]
constexpr int XS2_BHO     = 256 * 32 * 8;              // 65536
constexpr int XS2_BYTES   = XS2_BHO + 64 * 4;          // 65792

__global__ void __launch_bounds__(256, 2)
xgemm_kernel(const float* __restrict__ hout,    // [B, T+1, H]
             const float* __restrict__ x0,      // [B, DOUT]
             const float* __restrict__ W_ho,    // [64, 256]
             const float* __restrict__ b_ho,    // [64]
             float* __restrict__ xout)          // [B, T+1, DOUT]
{
    extern __shared__ char xsm[];
    uint64_t* wd  = (uint64_t*)(xsm + XS2_WD);   // [256 k][32 jp]
    float*    bho = (float*)(xsm + XS2_BHO);     // [64]

    const int tid = threadIdx.x;

    // W transpose fill: wd[k][jp] = (W_ho[2jp][k], W_ho[2jp+1][k])
    for (int idx = tid; idx < 256 * 32; idx += 256) {
        int k = idx >> 5, jp = idx & 31;
        wd[k * 32 + jp] = pk2(W_ho[(size_t)(2 * jp) * 256 + k],
                              W_ho[(size_t)(2 * jp + 1) * 256 + k]);
    }
    if (tid < 64) bho[tid] = b_ho[tid];
    __syncthreads();

    const int g = blockIdx.x * 256 + tid;        // 0 .. 131327, exact
    const int b = g / (RNN_T + 1);
    const int t = g - b * (RNN_T + 1);

    float* orow = xout + (size_t)g * RNN_DOUT;

    if (t == 0) {
        const float* src = x0 + (size_t)b * RNN_DOUT;
        #pragma unroll
        for (int c = 0; c < 16; c++)
            *(float4*)&orow[4 * c] = *(const float4*)&src[4 * c];
    } else {
        uint64_t acc[32];
        #pragma unroll
        for (int jp = 0; jp < 32; jp++)
            acc[jp] = pk2(bho[2 * jp], bho[2 * jp + 1]);

        const float4* hrow4 = (const float4*)(hout + (size_t)g * RNN_H);
        #pragma unroll 2
        for (int k4 = 0; k4 < 64; k4++) {
            float4 h4 = hrow4[k4];
            float hs4[4] = {h4.x, h4.y, h4.z, h4.w};
            #pragma unroll
            for (int i = 0; i < 4; i++) {
                uint64_t h2 = pk2(hs4[i], hs4[i]);
                const ulonglong2* wrow = (const ulonglong2*)(wd + (4 * k4 + i) * 32);
                #pragma unroll
                for (int jj = 0; jj < 16; jj++) {
                    ulonglong2 w = wrow[jj];
                    ffma2(acc[2 * jj],     w.x, h2);
                    ffma2(acc[2 * jj + 1], w.y, h2);
                }
            }
        }
        #pragma unroll
        for (int jp = 0; jp < 32; jp++)
            *(uint64_t*)&orow[2 * jp] = acc[jp];
    }
}

extern "C" void kernel_launch(void* const* d_in, const int* in_sizes, int n_in,
                              void* d_out, int out_size) {
    (void)in_sizes; (void)n_in; (void)out_size;
    const float* inputs = (const float*)d_in[0];
    const float* x0     = (const float*)d_in[1];
    const float* h0     = (const float*)d_in[2];
    const float* W_ih   = (const float*)d_in[3];
    const float* b_ih   = (const float*)d_in[4];
    const float* W_ho   = (const float*)d_in[5];
    const float* b_ho   = (const float*)d_in[6];

    float* xout = (float*)d_out;                                   // [B, T+1, DOUT]
    float* hout = xout + (size_t)RNN_B * (RNN_T + 1) * RNN_DOUT;   // [B, T+1, H]

    cudaFuncSetAttribute(rnn_scan_kernel,
                         cudaFuncAttributeMaxDynamicSharedMemorySize, SMEM_BYTES);
    cudaFuncSetAttribute(xgemm_kernel,
                         cudaFuncAttributeMaxDynamicSharedMemorySize, XS2_BYTES);

    rnn_scan_kernel<<<128, THREADS, SMEM_BYTES>>>(
        inputs, h0, W_ih, b_ih, hout);

    xgemm_kernel<<<XBLOCKS, 256, XS2_BYTES>>>(
        hout, x0, W_ho, b_ho, xout);
}